// round 12
// baseline (speedup 1.0000x reference)
#include <cuda_runtime.h>
#include <math.h>
#include <stdint.h>

#define NPB 65536
#define NT  131072

// ---------------- scratch ----------
__device__ float g_X [NT*64];
__device__ float g_Mk[NT*64];
__device__ float g_Q [NT*64];
__device__ float g_K [NT*64];
__device__ float g_V [NT*64];
__device__ float g_T1[NT*64];
__device__ float g_H1[NT*256];
__device__ float g_H2[NT*256];
__device__ float g_GP[2*128*1152];
__device__ float g_MC[2*64*64];

__device__ __forceinline__ float gelu_f(float u){
    return 0.5f*u*(1.f+erff(u*0.70710678118654752f));
}
__device__ __forceinline__ uint32_t tf32c(float f){
    uint32_t r; asm("cvt.rna.tf32.f32 %0, %1;" : "=r"(r) : "f"(f)); return r;
}
#define MMA_TF32(d, a, b0, b1) \
  asm volatile("mma.sync.aligned.m16n8k8.row.col.f32.tf32.tf32.f32 " \
    "{%0,%1,%2,%3},{%4,%5,%6,%7},{%8,%9},{%0,%1,%2,%3};" \
    : "+f"((d)[0]),"+f"((d)[1]),"+f"((d)[2]),"+f"((d)[3]) \
    : "r"((a)[0]),"r"((a)[1]),"r"((a)[2]),"r"((a)[3]),"r"(b0),"r"(b1))

#define XS_STRIDE 68
#define WS_STRIDE 72
#define XS_U (128*XS_STRIDE)
#define WS_U (64*WS_STRIDE)
#define TM_SMEM ((XS_U + WS_U + 64)*4)

// ---------------- tf32 tensor GEMM -----------------------------------------
// Tile 128px(M) x 64out(N), K=64/chunk. 128 threads = 4 warps.
// KC: K chunks. NC: N chunks. MODE: 0 store,1 gelu,2 add.
// FUSE: 0 plain, 1 LayerNorm on X during staging (xa=gamma,xb=beta).
template<int KC,int NC,int MODE,int FUSE>
__global__ __launch_bounds__(128, 4) void k_tmma(
        const float* __restrict__ X, int xStride,
        const float* __restrict__ W, int wStride, int wBatchStride,
        const float* __restrict__ bias,
        const float* __restrict__ xa, const float* __restrict__ xb,
        float* __restrict__ OUT, int oStride){
    extern __shared__ uint32_t smu[];
    uint32_t* xs = smu;
    uint32_t* ws = smu + XS_U;
    float*    sb = (float*)(smu + XS_U + WS_U);
    const int t = threadIdx.x;
    const int warp = t>>5, lane = t&31;
    const int lr = lane>>2, lc = lane&3;
    const int m0 = warp*32;
    const int c4f = t&15;
    const size_t tileBase = (size_t)blockIdx.x*128;
    const float* Wb = W + (wBatchStride ? (int)(tileBase>>16)*(size_t)wBatchStride : 0);
    if(bias && t<64) sb[t] = bias[t];

    float4 g4, b4;
    if(FUSE==1){
        g4 = *(const float4*)(xa + c4f*4);
        b4 = *(const float4*)(xb + c4f*4);
    }

    float acc[64];
    const int CH = (KC>NC)?KC:NC;

    for(int c=0;c<CH;c++){
        const int kOff = (KC>1)? c*64 : 0;
        const int nOff = (NC>1)? c*64 : 0;
        if(c) __syncthreads();
        if(c==0 || KC>1){
            #pragma unroll
            for(int it=0;it<16;it++){
                int s4 = t + it*128;
                int p = s4>>4, c4 = s4&15;
                float4 v = *(const float4*)(X + (tileBase+p)*(size_t)xStride + kOff + c4*4);
                if(FUSE==1){
                    float s1 = v.x+v.y+v.z+v.w;
                    float s2 = v.x*v.x+v.y*v.y+v.z*v.z+v.w*v.w;
                    #pragma unroll
                    for(int sw=1;sw<16;sw<<=1){
                        s1 += __shfl_xor_sync(0xffffffffu, s1, sw);
                        s2 += __shfl_xor_sync(0xffffffffu, s2, sw);
                    }
                    float mu = s1*(1.f/64.f);
                    float var = fmaxf(s2*(1.f/64.f) - mu*mu, 0.f);
                    float rs = rsqrtf(var + 1e-5f);
                    v.x = (v.x-mu)*rs*g4.x + b4.x;
                    v.y = (v.y-mu)*rs*g4.y + b4.y;
                    v.z = (v.z-mu)*rs*g4.z + b4.z;
                    v.w = (v.w-mu)*rs*g4.w + b4.w;
                }
                uint32_t* xr = xs + p*XS_STRIDE + c4*4;
                xr[0]=tf32c(v.x); xr[1]=tf32c(v.y); xr[2]=tf32c(v.z); xr[3]=tf32c(v.w);
            }
        }
        #pragma unroll
        for(int it=0;it<32;it++){
            int s = t + it*128;
            int o = s&63, j = s>>6;
            ws[j*WS_STRIDE+o] = tf32c(Wb[(size_t)(kOff+j)*wStride + nOff + o]);
        }
        __syncthreads();
        if(c==0 || NC>1){
            if(bias){
                #pragma unroll
                for(int mt=0;mt<2;mt++)
                    #pragma unroll
                    for(int j=0;j<8;j++){
                        float b0 = sb[j*8 + 2*lc], b1 = sb[j*8 + 2*lc + 1];
                        acc[mt*32+j*4+0]=b0; acc[mt*32+j*4+1]=b1;
                        acc[mt*32+j*4+2]=b0; acc[mt*32+j*4+3]=b1;
                    }
            } else {
                #pragma unroll
                for(int q=0;q<64;q++) acc[q]=0.f;
            }
        }
        #pragma unroll
        for(int k0=0;k0<64;k0+=8){
            uint32_t a[2][4];
            #pragma unroll
            for(int mt=0;mt<2;mt++){
                const uint32_t* xbp = xs + (m0+mt*16+lr)*XS_STRIDE + k0 + lc;
                a[mt][0]=xbp[0]; a[mt][1]=xbp[8*XS_STRIDE];
                a[mt][2]=xbp[4]; a[mt][3]=xbp[8*XS_STRIDE+4];
            }
            #pragma unroll
            for(int j=0;j<8;j++){
                uint32_t b0 = ws[(k0+lc  )*WS_STRIDE + j*8 + lr];
                uint32_t b1 = ws[(k0+lc+4)*WS_STRIDE + j*8 + lr];
                MMA_TF32(acc +      j*4, a[0], b0, b1);
                MMA_TF32(acc + 32 + j*4, a[1], b0, b1);
            }
        }
        if(NC>1 || c==CH-1){
            #pragma unroll
            for(int mt=0;mt<2;mt++){
                #pragma unroll
                for(int j=0;j<8;j++){
                    size_t row = tileBase + m0 + mt*16 + lr;
                    int col = nOff + j*8 + 2*lc;
                    float v0=acc[mt*32+j*4], v1=acc[mt*32+j*4+1];
                    float v2=acc[mt*32+j*4+2], v3=acc[mt*32+j*4+3];
                    if(MODE==1){ v0=gelu_f(v0); v1=gelu_f(v1); v2=gelu_f(v2); v3=gelu_f(v3); }
                    float* p0 = OUT + row*(size_t)oStride + col;
                    float* p8 = p0 + 8*(size_t)oStride;
                    if(MODE==2){
                        float2 o0 = *(float2*)p0, o8 = *(float2*)p8;
                        v0+=o0.x; v1+=o0.y; v2+=o8.x; v3+=o8.y;
                    }
                    *(float2*)p0 = make_float2(v0,v1);
                    *(float2*)p8 = make_float2(v2,v3);
                }
            }
        }
    }
}

// ---------------- gram partials via mma tf32 -------------------------------
// Block: 512 px, 256 threads. Per 64-px chunk: warps 0-3 do head-w 16x16
// gram via m16n8k8 (K^T @ Q over px); warps 4-7 do Q/K channel norms.
#define GR_STRIDE 68
__global__ __launch_bounds__(256) void k_gram(const float* __restrict__ Q,
        const float* __restrict__ K, float* __restrict__ gpart){
    __shared__ float sq[64*GR_STRIDE], sk[64*GR_STRIDE];
    const int t=threadIdx.x, warp=t>>5, lane=t&31;
    const int lr=lane>>2, lc=lane&3;
    const int b=blockIdx.y;
    const int h = warp&3;
    const int nb = (warp&1)*32;
    float accS[8];
    #pragma unroll
    for(int i=0;i<8;i++) accS[i]=0.f;
    float nrm=0.f;

    for(int ch=0; ch<8; ch++){
        size_t base = ((size_t)b*NPB + (size_t)blockIdx.x*512 + ch*64)*64;
        __syncthreads();
        #pragma unroll
        for(int it=0; it<4; it++){
            int s4 = t + it*256;
            int p = s4>>4, c4 = s4&15;
            float4 v = *(const float4*)(Q + base + p*64 + c4*4);
            float* r = sq + p*GR_STRIDE + c4*4;
            r[0]=v.x; r[1]=v.y; r[2]=v.z; r[3]=v.w;
            float4 w = *(const float4*)(K + base + p*64 + c4*4);
            float* r2 = sk + p*GR_STRIDE + c4*4;
            r2[0]=w.x; r2[1]=w.y; r2[2]=w.z; r2[3]=w.w;
        }
        __syncthreads();
        if(warp<4){
            #pragma unroll
            for(int k0=0;k0<64;k0+=8){
                uint32_t a[4];
                a[0]=tf32c(sk[(k0+lc  )*GR_STRIDE + h*16+lr  ]);
                a[1]=tf32c(sk[(k0+lc  )*GR_STRIDE + h*16+lr+8]);
                a[2]=tf32c(sk[(k0+lc+4)*GR_STRIDE + h*16+lr  ]);
                a[3]=tf32c(sk[(k0+lc+4)*GR_STRIDE + h*16+lr+8]);
                #pragma unroll
                for(int nt=0;nt<2;nt++){
                    uint32_t b0=tf32c(sq[(k0+lc  )*GR_STRIDE + h*16+nt*8+lr]);
                    uint32_t b1=tf32c(sq[(k0+lc+4)*GR_STRIDE + h*16+nt*8+lr]);
                    MMA_TF32(accS+nt*4, a, b0, b1);
                }
            }
        } else {
            const float* s = (warp<6)? sq : sk;
            int c = nb + lane;
            #pragma unroll 8
            for(int p=0;p<64;p++){ float v=s[p*GR_STRIDE+c]; nrm += v*v; }
        }
    }
    float* gp = gpart + ((size_t)b*128 + blockIdx.x)*1152;
    if(warp<4){
        float* gs = gp + h*256;
        #pragma unroll
        for(int nt=0;nt<2;nt++){
            int e0 = nt*8 + 2*lc;
            gs[lr*16 + e0]       = accS[nt*4+0];
            gs[lr*16 + e0+1]     = accS[nt*4+1];
            gs[(lr+8)*16 + e0]   = accS[nt*4+2];
            gs[(lr+8)*16 + e0+1] = accS[nt*4+3];
        }
    } else {
        int off = (warp<6)? 1024 : 1088;
        gp[off + nb + lane] = nrm;
    }
}

// ---------------- attn softmax + fold into Mcomb ---------------------------
__global__ __launch_bounds__(256) void k_attn(const float* __restrict__ gpart,
        const float* __restrict__ Wp, const float* __restrict__ resc,
        float* __restrict__ Mcomb){
    __shared__ float sred[2304];
    __shared__ float sa[2048];
    int tid = threadIdx.x;
    for(int jj=tid;jj<2304;jj+=256){
        int b=jj/1152, j=jj-b*1152;
        float acc=0.f;
        for(int blk=0;blk<128;blk++) acc += gpart[((size_t)b*128+blk)*1152 + j];
        sred[jj]=acc;
    }
    __syncthreads();
    if(tid<128){
        int b=tid>>6, hd=tid&63, h=hd>>4, d=hd&15;
        float nk = fmaxf(sqrtf(sred[b*1152+1088+hd]),1e-6f);
        float r = resc[h];
        float row[16]; float mx=-1e30f;
        #pragma unroll
        for(int e=0;e<16;e++){
            float nq = fmaxf(sqrtf(sred[b*1152+1024+h*16+e]),1e-6f);
            float v = sred[b*1152 + h*256 + d*16 + e] / (nk*nq) * r;
            row[e]=v; mx=fmaxf(mx,v);
        }
        float s=0.f;
        #pragma unroll
        for(int e=0;e<16;e++){ row[e]=expf(row[e]-mx); s+=row[e]; }
        float inv=1.f/s;
        #pragma unroll
        for(int e=0;e<16;e++) sa[((b*4+h)*16+d)*16+e] = row[e]*inv;
    }
    __syncthreads();
    for(int job=tid;job<8192;job+=256){
        int b=job>>12, rem=job&4095, ci=rem>>6, co=rem&63;
        int h=ci>>4, e=ci&15;
        float acc=0.f;
        #pragma unroll
        for(int d=0;d<16;d++) acc += sa[((b*4+h)*16+d)*16+e] * Wp[(h*16+d)*64+co];
        Mcomb[job]=acc;
    }
}

// ---------------- transposes ----------------
__global__ __launch_bounds__(256) void k_nchw2nhwc(const float* __restrict__ in, float* __restrict__ out){
    __shared__ float t[32][33];
    int tx = threadIdx.x & 31, ty = threadIdx.x >> 5;
    int pt = blockIdx.x, ct = blockIdx.y, b = blockIdx.z;
    const float* ip = in  + (size_t)b*64*NPB;
    float*       op = out + (size_t)b*NPB*64;
    #pragma unroll
    for(int r=0;r<4;r++){
        int c = ct*32 + ty + r*8;
        t[ty+r*8][tx] = ip[(size_t)c*NPB + (size_t)pt*32 + tx];
    }
    __syncthreads();
    #pragma unroll
    for(int r=0;r<4;r++){
        int p = pt*32 + ty + r*8;
        op[(size_t)p*64 + ct*32 + tx] = t[tx][ty+r*8];
    }
}
__global__ __launch_bounds__(256) void k_nhwc2nchw(const float* __restrict__ in, float* __restrict__ out){
    __shared__ float t[32][33];
    int tx = threadIdx.x & 31, ty = threadIdx.x >> 5;
    int pt = blockIdx.x, ct = blockIdx.y, b = blockIdx.z;
    const float* ip = in  + (size_t)b*NPB*64;
    float*       op = out + (size_t)b*64*NPB;
    #pragma unroll
    for(int r=0;r<4;r++){
        int p = pt*32 + ty + r*8;
        t[ty+r*8][tx] = ip[(size_t)p*64 + ct*32 + tx];
    }
    __syncthreads();
    #pragma unroll
    for(int r=0;r<4;r++){
        int c = ct*32 + ty + r*8;
        op[(size_t)c*NPB + (size_t)pt*32 + tx] = t[tx][ty+r*8];
    }
}

// ---------------- mask gate (float4) ---------------------------------------
__global__ __launch_bounds__(256) void k_maskgate(const float* __restrict__ T,
        const float* __restrict__ M1, const float* __restrict__ V,
        const float* __restrict__ dw, const float* __restrict__ db,
        float* __restrict__ VG){
    __shared__ float4 sdw[400];
    __shared__ float4 sdb4[16];
    int tid=threadIdx.x;
    for(int i=tid;i<400;i+=256) sdw[i]=((const float4*)dw)[i];
    if(tid<16) sdb4[tid]=((const float4*)db)[tid];
    __syncthreads();
    size_t e=(size_t)blockIdx.x*256+tid;
    int c4=(int)(e&15);
    size_t p=e>>4;
    int b=(int)(p>>16);
    int pp=(int)(p&65535);
    int y=pp>>8, x=pp&255;
    float4 conv=make_float4(0,0,0,0);
    #pragma unroll
    for(int dy=0;dy<5;dy++){
        int yy=y+dy-2; if(yy<0||yy>255) continue;
        #pragma unroll
        for(int dx=0;dx<5;dx++){
            int xx=x+dx-2; if(xx<0||xx>255) continue;
            float4 tv = *(const float4*)(T + (((((size_t)b<<16)+(yy<<8)+xx)<<6)+c4*4));
            float4 wv = sdw[(dy*5+dx)*16+c4];
            conv.x+=tv.x*wv.x; conv.y+=tv.y*wv.y; conv.z+=tv.z*wv.z; conv.w+=tv.w*wv.w;
        }
    }
    float4 bb=sdb4[c4];
    float4 m1=((const float4*)M1)[e];
    float4 vv=((const float4*)V)[e];
    float4 r;
    r.x = vv.x*m1.x*(1.f+1.f/(1.f+expf(-(conv.x+bb.x))));
    r.y = vv.y*m1.y*(1.f+1.f/(1.f+expf(-(conv.y+bb.y))));
    r.z = vv.z*m1.z*(1.f+1.f/(1.f+expf(-(conv.z+bb.z))));
    r.w = vv.w*m1.w*(1.f+1.f/(1.f+expf(-(conv.w+bb.w))));
    ((float4*)VG)[e]=r;
}

// ---------------- depthwise 3x3 + GELU (float4, C=1<<cbits) ----------------
__global__ __launch_bounds__(256) void k_dw3_gelu(const float* __restrict__ in,
        const float* __restrict__ dw, float* __restrict__ out, int cbits){
    __shared__ float4 sdw[576];
    int tid=threadIdx.x;
    int C4=1<<(cbits-2);
    for(int i=tid;i<9*C4;i+=256) sdw[i]=((const float4*)dw)[i];
    __syncthreads();
    size_t e=(size_t)blockIdx.x*256+tid;
    int c4=(int)(e&(C4-1));
    size_t p=e>>(cbits-2);
    int b=(int)(p>>16), pp=(int)(p&65535), y=pp>>8, x=pp&255;
    float4 conv=make_float4(0,0,0,0);
    #pragma unroll
    for(int dy=0;dy<3;dy++){
        int yy=y+dy-1; if(yy<0||yy>255) continue;
        #pragma unroll
        for(int dx=0;dx<3;dx++){
            int xx=x+dx-1; if(xx<0||xx>255) continue;
            float4 tv = *(const float4*)(in + ((((((size_t)b<<16)+(yy<<8)+xx))<<cbits)+c4*4));
            float4 wv = sdw[(dy*3+dx)*C4+c4];
            conv.x+=tv.x*wv.x; conv.y+=tv.y*wv.y; conv.z+=tv.z*wv.z; conv.w+=tv.w*wv.w;
        }
    }
    float4 r=make_float4(gelu_f(conv.x),gelu_f(conv.y),gelu_f(conv.z),gelu_f(conv.w));
    ((float4*)out)[e]=r;
}

// ---------------- msa epilogue: X += dw3(P, pe2) (float4) ------------------
__global__ __launch_bounds__(256) void k_msa_out(
        const float* __restrict__ P, const float* __restrict__ pe2,
        float* __restrict__ X){
    __shared__ float4 sdw[144];
    int tid=threadIdx.x;
    if(tid<144) sdw[tid]=((const float4*)pe2)[tid];
    __syncthreads();
    size_t e=(size_t)blockIdx.x*256+tid;
    int c4=(int)(e&15);
    size_t p=e>>4;
    int b=(int)(p>>16), pp=(int)(p&65535), y=pp>>8, x=pp&255;
    float4 conv=make_float4(0,0,0,0);
    #pragma unroll
    for(int dy=0;dy<3;dy++){
        int yy=y+dy-1; if(yy<0||yy>255) continue;
        #pragma unroll
        for(int dx=0;dx<3;dx++){
            int xx=x+dx-1; if(xx<0||xx>255) continue;
            float4 tv = *(const float4*)(P + (((((size_t)b<<16)+(yy<<8)+xx)<<6)+c4*4));
            float4 wv = sdw[(dy*3+dx)*16+c4];
            conv.x+=tv.x*wv.x; conv.y+=tv.y*wv.y; conv.z+=tv.z*wv.z; conv.w+=tv.w*wv.w;
        }
    }
    float4 xv=((float4*)X)[e];
    xv.x+=conv.x; xv.y+=conv.y; xv.z+=conv.z; xv.w+=conv.w;
    ((float4*)X)[e]=xv;
}

// ---------------- host -----------------------------------------------------
extern "C" void kernel_launch(void* const* d_in, const int* in_sizes, int n_in,
                              void* d_out, int out_size){
    const float* x    = (const float*)d_in[0];
    const float* mask = (const float*)d_in[1];
    const float* Wq   = (const float*)d_in[2];
    const float* Wk   = (const float*)d_in[3];
    const float* Wv   = (const float*)d_in[4];
    const float* resc = (const float*)d_in[5];
    const float* Wp   = (const float*)d_in[6];
    const float* bp   = (const float*)d_in[7];
    const float* pe1  = (const float*)d_in[8];
    const float* pe2  = (const float*)d_in[9];
    const float* mw1  = (const float*)d_in[10];
    const float* mb1  = (const float*)d_in[11];
    const float* mw2  = (const float*)d_in[12];
    const float* mb2  = (const float*)d_in[13];
    const float* mdw  = (const float*)d_in[14];
    const float* mdb  = (const float*)d_in[15];
    const float* lng  = (const float*)d_in[16];
    const float* lnb  = (const float*)d_in[17];
    const float* fw1  = (const float*)d_in[18];
    const float* fdw  = (const float*)d_in[19];
    const float* fw2  = (const float*)d_in[20];
    float* out = (float*)d_out;

    float *pX,*pM,*pQ,*pK,*pV,*pT1,*pH1,*pH2,*pGP,*pMC;
    cudaGetSymbolAddress((void**)&pX,  g_X);
    cudaGetSymbolAddress((void**)&pM,  g_Mk);
    cudaGetSymbolAddress((void**)&pQ,  g_Q);
    cudaGetSymbolAddress((void**)&pK,  g_K);
    cudaGetSymbolAddress((void**)&pV,  g_V);
    cudaGetSymbolAddress((void**)&pT1, g_T1);
    cudaGetSymbolAddress((void**)&pH1, g_H1);
    cudaGetSymbolAddress((void**)&pH2, g_H2);
    cudaGetSymbolAddress((void**)&pGP, g_GP);
    cudaGetSymbolAddress((void**)&pMC, g_MC);

    cudaFuncSetAttribute(k_tmma<1,1,0,0>, cudaFuncAttributeMaxDynamicSharedMemorySize, TM_SMEM);
    cudaFuncSetAttribute(k_tmma<1,1,2,0>, cudaFuncAttributeMaxDynamicSharedMemorySize, TM_SMEM);
    cudaFuncSetAttribute(k_tmma<1,4,1,1>, cudaFuncAttributeMaxDynamicSharedMemorySize, TM_SMEM);
    cudaFuncSetAttribute(k_tmma<4,1,2,0>, cudaFuncAttributeMaxDynamicSharedMemorySize, TM_SMEM);

    dim3 tg(2048,2,2);
    k_nchw2nhwc<<<tg,256>>>(x,    pX);
    k_nchw2nhwc<<<tg,256>>>(mask, pM);

    for(int i=0;i<3;i++){
        const float* Wq_i  = Wq  + i*4096;
        const float* Wk_i  = Wk  + i*4096;
        const float* Wv_i  = Wv  + i*4096;
        const float* Wp_i  = Wp  + i*4096;
        const float* mw1_i = mw1 + i*4096;
        const float* mw2_i = mw2 + i*4096;
        const float* bp_i  = bp  + i*64;
        const float* mb1_i = mb1 + i*64;
        const float* mb2_i = mb2 + i*64;
        const float* mdb_i = mdb + i*64;
        const float* lng_i = lng + i*64;
        const float* lnb_i = lnb + i*64;
        const float* pe1_i = pe1 + i*576;
        const float* pe2_i = pe2 + i*576;
        const float* mdw_i = mdw + i*1600;
        const float* rs_i  = resc+ i*4;
        const float* fw1_i = fw1 + i*64*256;
        const float* fdw_i = fdw + i*9*256;
        const float* fw2_i = fw2 + i*256*64;

        // attention stats path (split projections, mma gram)
        k_tmma<1,1,0,0><<<1024,128,TM_SMEM>>>(pX, 64, Wq_i, 64, 0, nullptr, nullptr, nullptr, pQ, 64);
        k_tmma<1,1,0,0><<<1024,128,TM_SMEM>>>(pX, 64, Wk_i, 64, 0, nullptr, nullptr, nullptr, pK, 64);
        k_gram<<<dim3(128,2),256>>>(pQ, pK, pGP);
        k_attn<<<1,256>>>(pGP, Wp_i, rs_i, pMC);
        // v + mask gate
        k_tmma<1,1,0,0><<<1024,128,TM_SMEM>>>(pX, 64, Wv_i, 64, 0, nullptr, nullptr, nullptr, pV, 64);
        k_tmma<1,1,0,0><<<1024,128,TM_SMEM>>>(pM, 64, mw1_i, 64, 0, mb1_i, nullptr, nullptr, pT1, 64);
        k_tmma<1,1,0,0><<<1024,128,TM_SMEM>>>(pT1, 64, mw2_i, 64, 0, mb2_i, nullptr, nullptr, pQ, 64);
        k_maskgate<<<8192,256>>>(pQ, pT1, pV, mdw_i, mdb_i, pT1);    // VG -> g_T1
        // positional path
        k_dw3_gelu<<<8192,256>>>(pV, pe1_i, pK, 6);                  // P -> g_K
        // folded attention apply + proj, added straight into X
        k_tmma<1,1,2,0><<<1024,128,TM_SMEM>>>(pT1, 64, pMC, 64, 4096, bp_i, nullptr, nullptr, pX, 64);
        k_msa_out<<<8192,256>>>(pK, pe2_i, pX);                      // X += dw3(P)
        // feed-forward: LN fused into ff1 staging
        k_tmma<1,4,1,1><<<1024,128,TM_SMEM>>>(pX, 64, fw1_i, 256, 0, nullptr, lng_i, lnb_i, pH1, 256);
        k_dw3_gelu<<<32768,256>>>(pH1, fdw_i, pH2, 8);
        k_tmma<4,1,2,0><<<1024,128,TM_SMEM>>>(pH2, 256, fw2_i, 64, 0, nullptr, nullptr, nullptr, pX, 64);
    }

    k_nhwc2nchw<<<tg,256>>>(pX, out);
}